// round 8
// baseline (speedup 1.0000x reference)
#include <cuda_runtime.h>
#include <cuda_bf16.h>
#include <cstdint>

// LSTMNet: B=1024, T=2048, H=64, NC=10
// CTA = 256 threads handles TWO batch elements (grid 512).
// Thread t: hid = t>>2, gate = t&3 (0=i,1=f,2=g,3=o), row r = gate*64+hid.
// W_hh row in 32 packed u64 regs, SHARED between both batch streams.
// Activations via MUFU.TANH (tanh.approx.f32); sigma(z)=0.5*tanh(z/2)+0.5.
// Cell update + tanh(c) + h store done ONLY by the gate==3 lane of each quad.
// One __syncthreads per timestep covering both batch streams.

#define T_LEN 2048
#define HDIM  64
#define NCLS  10

#define FMA2(acc, a, b) \
    asm("fma.rn.f32x2 %0, %1, %2, %0;" : "+l"(acc) : "l"(a), "l"(b))
#define ADD2(d, a, b) \
    asm("add.rn.f32x2 %0, %1, %2;" : "=l"(d) : "l"(a), "l"(b))

__device__ __forceinline__ float tanh_fast(float z) {
    float r;
    asm("tanh.approx.f32 %0, %1;" : "=f"(r) : "f"(z));
    return r;
}

__global__ __launch_bounds__(256, 2)
void lstm_net_kernel(const float* __restrict__ x,
                     const float* __restrict__ W_ih,
                     const float* __restrict__ W_hh,
                     const float* __restrict__ b_ih,
                     const float* __restrict__ b_hh,
                     const float* __restrict__ fc1_w,
                     const float* __restrict__ fc1_b,
                     const float* __restrict__ fc2_w,
                     const float* __restrict__ fc2_b,
                     float* __restrict__ out)
{
    __shared__ __align__(16) float sxA[T_LEN];     // batch elem A's x row (8 KB)
    __shared__ __align__(16) float sxB[T_LEN];     // batch elem B's x row (8 KB)
    __shared__ __align__(16) float shA[2][HDIM];   // double-buffered hidden, A
    __shared__ __align__(16) float shB[2][HDIM];   // double-buffered hidden, B
    __shared__ __align__(16) float s1A[HDIM];      // fc1 out A
    __shared__ __align__(16) float s1B[HDIM];      // fc1 out B

    const int bA   = 2 * blockIdx.x;
    const int bB   = bA + 1;
    const int t    = threadIdx.x;
    const int hid  = t >> 2;
    const int gate = t & 3;
    const int r    = gate * HDIM + hid;            // row in the 4H-stacked params

    // ---- stage x rows into smem (coalesced float4) ----
    {
        const float4* xA = reinterpret_cast<const float4*>(x + (size_t)bA * T_LEN);
        const float4* xB = reinterpret_cast<const float4*>(x + (size_t)bB * T_LEN);
        float4* sA4 = reinterpret_cast<float4*>(sxA);
        float4* sB4 = reinterpret_cast<float4*>(sxB);
        #pragma unroll
        for (int i = t; i < T_LEN / 4; i += 256) { sA4[i] = xA[i]; sB4[i] = xB[i]; }
    }

    // ---- W_hh row -> 32 packed (f32,f32) registers (shared across both streams) ----
    unsigned long long wp[32];
    {
        const ulonglong2* wrow = reinterpret_cast<const ulonglong2*>(W_hh + (size_t)r * HDIM);
        #pragma unroll
        for (int q = 0; q < 16; q++) {
            ulonglong2 v = wrow[q];
            wp[2 * q]     = v.x;
            wp[2 * q + 1] = v.y;
        }
    }
    const float w_in = W_ih[r];
    const float bias = b_ih[r] + b_hh[r];

    // branchless activation: sigmoid(z) = 0.5*tanh(0.5z)+0.5 ; gate 2 uses tanh(z)
    const float zs = (gate == 2) ? 1.0f : 0.5f;
    const float aa = (gate == 2) ? 1.0f : 0.5f;
    const float ab = (gate == 2) ? 0.0f : 0.5f;
    const bool  owner = (gate == 3);               // lane holding o does the cell update

    if (t < HDIM) shA[0][t] = 0.0f;
    else if (t < 2 * HDIM) shB[0][t - HDIM] = 0.0f;
    float cA = 0.0f, cB = 0.0f;
    __syncthreads();

    #pragma unroll 1
    for (int step = 0; step < T_LEN; step++) {
        const int p  = step & 1;
        const int np = p ^ 1;

        const float preA = fmaf(sxA[step], w_in, bias);
        const float preB = fmaf(sxB[step], w_in, bias);

        unsigned long long aA0 = (unsigned long long)__float_as_uint(preA);
        unsigned long long aB0 = (unsigned long long)__float_as_uint(preB);
        unsigned long long aA1 = 0ull, aA2 = 0ull, aA3 = 0ull;
        unsigned long long aB1 = 0ull, aB2 = 0ull, aB3 = 0ull;

        const ulonglong2* hpA = reinterpret_cast<const ulonglong2*>(shA[p]);
        const ulonglong2* hpB = reinterpret_cast<const ulonglong2*>(shB[p]);

        #pragma unroll 4
        for (int q = 0; q < 16; q++) {
            ulonglong2 vA = hpA[q];                // LDS.128 broadcast
            ulonglong2 vB = hpB[q];
            if (q & 1) {
                FMA2(aA2, wp[2 * q],     vA.x);
                FMA2(aA3, wp[2 * q + 1], vA.y);
                FMA2(aB2, wp[2 * q],     vB.x);
                FMA2(aB3, wp[2 * q + 1], vB.y);
            } else {
                FMA2(aA0, wp[2 * q],     vA.x);
                FMA2(aA1, wp[2 * q + 1], vA.y);
                FMA2(aB0, wp[2 * q],     vB.x);
                FMA2(aB1, wp[2 * q + 1], vB.y);
            }
        }

        unsigned long long sA01, sA23, sA, sB01, sB23, sB;
        ADD2(sA01, aA0, aA1);  ADD2(sA23, aA2, aA3);  ADD2(sA, sA01, sA23);
        ADD2(sB01, aB0, aB1);  ADD2(sB23, aB2, aB3);  ADD2(sB, sB01, sB23);
        const float gsA = __uint_as_float((unsigned)sA) + __uint_as_float((unsigned)(sA >> 32));
        const float gsB = __uint_as_float((unsigned)sB) + __uint_as_float((unsigned)(sB >> 32));

        // one MUFU.TANH per gate per stream
        const float actA = fmaf(tanh_fast(gsA * zs), aa, ab);
        const float actB = fmaf(tanh_fast(gsB * zs), aa, ab);

        // gather i, f, g into the quad's o-lane (lane 3 of each quad)
        const float iA = __shfl_sync(0xffffffffu, actA, 0, 4);
        const float fA = __shfl_sync(0xffffffffu, actA, 1, 4);
        const float gA = __shfl_sync(0xffffffffu, actA, 2, 4);
        const float iB = __shfl_sync(0xffffffffu, actB, 0, 4);
        const float fB = __shfl_sync(0xffffffffu, actB, 1, 4);
        const float gB = __shfl_sync(0xffffffffu, actB, 2, 4);

        if (owner) {
            cA = fmaf(fA, cA, iA * gA);
            cB = fmaf(fB, cB, iB * gB);
            shA[np][hid] = actA * tanh_fast(cA);   // actA = sigmoid(o) here
            shB[np][hid] = actB * tanh_fast(cB);
        }
        __syncthreads();
    }

    // T_LEN even: final h lives in buffer 0
    const float* hfA = shA[0];
    const float* hfB = shB[0];

    // ---- fc1 + relu: threads 0..63 do A, 64..127 do B ----
    if (t < HDIM) {
        float a = fc1_b[t];
        const float* wr = fc1_w + t * HDIM;
        #pragma unroll 16
        for (int k = 0; k < HDIM; k++) a = fmaf(wr[k], hfA[k], a);
        s1A[t] = fmaxf(a, 0.0f);
    } else if (t < 2 * HDIM) {
        const int j = t - HDIM;
        float a = fc1_b[j];
        const float* wr = fc1_w + j * HDIM;
        #pragma unroll 16
        for (int k = 0; k < HDIM; k++) a = fmaf(wr[k], hfB[k], a);
        s1B[j] = fmaxf(a, 0.0f);
    }
    __syncthreads();

    // ---- fc2: threads 0..9 do A, 64..73 do B ----
    if (t < NCLS) {
        float a = fc2_b[t];
        const float* wr = fc2_w + t * HDIM;
        #pragma unroll 16
        for (int k = 0; k < HDIM; k++) a = fmaf(wr[k], s1A[k], a);
        out[(size_t)bA * NCLS + t] = a;
    } else if (t >= HDIM && t < HDIM + NCLS) {
        const int j = t - HDIM;
        float a = fc2_b[j];
        const float* wr = fc2_w + j * HDIM;
        #pragma unroll 16
        for (int k = 0; k < HDIM; k++) a = fmaf(wr[k], s1B[k], a);
        out[(size_t)bB * NCLS + j] = a;
    }
}

extern "C" void kernel_launch(void* const* d_in, const int* in_sizes, int n_in,
                              void* d_out, int out_size)
{
    const float* x     = (const float*)d_in[0];
    const float* W_ih  = (const float*)d_in[1];
    const float* W_hh  = (const float*)d_in[2];
    const float* b_ih  = (const float*)d_in[3];
    const float* b_hh  = (const float*)d_in[4];
    const float* fc1_w = (const float*)d_in[5];
    const float* fc1_b = (const float*)d_in[6];
    const float* fc2_w = (const float*)d_in[7];
    const float* fc2_b = (const float*)d_in[8];
    float* out = (float*)d_out;

    const int B = in_sizes[0] / T_LEN;   // 1024

    lstm_net_kernel<<<B / 2, 256>>>(x, W_ih, W_hh, b_ih, b_hh,
                                    fc1_w, fc1_b, fc2_w, fc2_b, out);
}